// round 15
// baseline (speedup 1.0000x reference)
#include <cuda_runtime.h>

// FSQ_80599356277526 — FINAL.
// Best measured: 12.74us timed / 12.16us ncu; identical binary spans
// 12.16-12.83us ncu across 5 replicates (B300 LTS-cap run-to-run noise).
//
// x (64, 32768, 4) fp32, N = 2097152 tokens, LEVELS = [8,5,5,5].
// out fp32 planes: out[d*N + n] = level_d(idx_d), out[4*N + n] = code (as
// float), code = i0 + 8*i1 + 40*i2 + 200*i3.
// One thread = 4 tokens: 2x LDG.256 (64B contiguous/thread), 5x STG.128
// (one fully-coalesced float4 per plane per warp -> 512B/warp/plane).
// Quantizer: (tanh(x)+1)/2 = rcp(1+ex2(-2x*log2e)); idx = rint(r*(L-1));
// q = idx*step - 1. Exact saturation at +/-1; rel_err 3.6e-8 (threshold 1e-3).
//
// Roofline: 72MB mandatory L1<->L2 traffic at up to 5.92TB/s = ~94% of the
// B300 path-independent LTS chip cap (~6300 B/cyc; identical for LDG and
// TMA paths, so no async/TMA rewrite can exceed it). 14 rounds, 9 distinct
// configurations: per-plane store coalescing and occupancy >= ~70% are the
// only levers that matter; compute cost, load/store width, tokens/thread,
// grid shape, block size, and cache hints all neutral or negative.

#define FSQ_N (64 * 32768)
#define NTHREADS 256
#define NBLOCKS (FSQ_N / 4 / NTHREADS)   // 2048

__device__ __forceinline__ float fast_ex2(float x) {
    float y;
    asm("ex2.approx.f32 %0, %1;" : "=f"(y) : "f"(x));
    return y;
}
__device__ __forceinline__ float fast_rcp(float x) {
    float y;
    asm("rcp.approx.f32 %0, %1;" : "=f"(y) : "f"(x));
    return y;
}

__device__ __forceinline__ int quant(float x, float scale, float step, float& q) {
    const float NEG2LOG2E = -2.8853900817779268f;  // -2*log2(e)
    float e = fast_ex2(x * NEG2LOG2E);             // e^(-2x)
    float r = fast_rcp(1.0f + e);                  // (tanh(x)+1)/2
    int idx = __float2int_rn(r * scale);
    q = (float)idx * step - 1.0f;
    return idx;
}

__device__ __forceinline__ void do_token(float x, float y, float z, float w,
                                         float& o0, float& o1, float& o2,
                                         float& o3, float& oc) {
    int i0 = quant(x, 7.0f, 2.0f / 7.0f, o0);
    int i1 = quant(y, 4.0f, 0.5f, o1);
    int i2 = quant(z, 4.0f, 0.5f, o2);
    int i3 = quant(w, 4.0f, 0.5f, o3);
    oc = (float)(i0 + 8 * i1 + 40 * i2 + 200 * i3);
}

// 256-bit global load (sm_100+): 8 fp32 per thread, contiguous.
__device__ __forceinline__ void ldg256(const float* p, float* r) {
    asm volatile(
        "ld.global.nc.v8.f32 {%0, %1, %2, %3, %4, %5, %6, %7}, [%8];"
        : "=f"(r[0]), "=f"(r[1]), "=f"(r[2]), "=f"(r[3]),
          "=f"(r[4]), "=f"(r[5]), "=f"(r[6]), "=f"(r[7])
        : "l"(p));
}

__global__ __launch_bounds__(NTHREADS) void fsq_kernel(const float* __restrict__ x,
                                                       float4* __restrict__ out4) {
    int t = blockIdx.x * NTHREADS + threadIdx.x;   // one thread = 4 tokens (16 floats)

    float v[16];
    ldg256(x + 16 * t, v);
    ldg256(x + 16 * t + 8, v + 8);

    float4 z0, z1, z2, z3, zc;
    do_token(v[0],  v[1],  v[2],  v[3],  z0.x, z1.x, z2.x, z3.x, zc.x);
    do_token(v[4],  v[5],  v[6],  v[7],  z0.y, z1.y, z2.y, z3.y, zc.y);
    do_token(v[8],  v[9],  v[10], v[11], z0.z, z1.z, z2.z, z3.z, zc.z);
    do_token(v[12], v[13], v[14], v[15], z0.w, z1.w, z2.w, z3.w, zc.w);

    const int PN4 = FSQ_N / 4;   // plane size in float4 units
    out4[0 * PN4 + t] = z0;
    out4[1 * PN4 + t] = z1;
    out4[2 * PN4 + t] = z2;
    out4[3 * PN4 + t] = z3;
    out4[4 * PN4 + t] = zc;
}

extern "C" void kernel_launch(void* const* d_in, const int* in_sizes, int n_in,
                              void* d_out, int out_size) {
    const float* x = (const float*)d_in[0];
    float4* out4 = (float4*)d_out;
    fsq_kernel<<<NBLOCKS, NTHREADS>>>(x, out4);
}

// round 16
// speedup vs baseline: 1.0305x; 1.0305x over previous
#include <cuda_runtime.h>

// FSQ_80599356277526 — final family; this round probes the one untested hint:
// st.global.L1::no_allocate on the 5 write-once output streams (L1 is the
// highest counter at ~40%; L2 policy untouched, unlike R3's harmful .cs).
//
// x (64, 32768, 4) fp32, N = 2097152 tokens, LEVELS = [8,5,5,5].
// out fp32 planes: out[d*N + n] = level_d(idx_d), out[4*N + n] = code (float),
// code = i0 + 8*i1 + 40*i2 + 200*i3.
// One thread = 4 tokens: 2x LDG.256 (64B contiguous/thread), 5x STG.128
// (one fully-coalesced float4 per plane per warp -> 512B/warp/plane).
// Quantizer: (tanh(x)+1)/2 = rcp(1+ex2(-2x*log2e)); idx = rint(r*(L-1));
// q = idx*step - 1. rel_err 3.6e-8 (threshold 1e-3).
//
// Roofline: 72MB mandatory L1<->L2 traffic at up to 5.92TB/s = ~94% of the
// B300 path-independent LTS chip cap (~6300 B/cyc; LDG == TMA path).

#define FSQ_N (64 * 32768)
#define NTHREADS 256
#define NBLOCKS (FSQ_N / 4 / NTHREADS)   // 2048

__device__ __forceinline__ float fast_ex2(float x) {
    float y;
    asm("ex2.approx.f32 %0, %1;" : "=f"(y) : "f"(x));
    return y;
}
__device__ __forceinline__ float fast_rcp(float x) {
    float y;
    asm("rcp.approx.f32 %0, %1;" : "=f"(y) : "f"(x));
    return y;
}

__device__ __forceinline__ int quant(float x, float scale, float step, float& q) {
    const float NEG2LOG2E = -2.8853900817779268f;  // -2*log2(e)
    float e = fast_ex2(x * NEG2LOG2E);             // e^(-2x)
    float r = fast_rcp(1.0f + e);                  // (tanh(x)+1)/2
    int idx = __float2int_rn(r * scale);
    q = (float)idx * step - 1.0f;
    return idx;
}

__device__ __forceinline__ void do_token(float x, float y, float z, float w,
                                         float& o0, float& o1, float& o2,
                                         float& o3, float& oc) {
    int i0 = quant(x, 7.0f, 2.0f / 7.0f, o0);
    int i1 = quant(y, 4.0f, 0.5f, o1);
    int i2 = quant(z, 4.0f, 0.5f, o2);
    int i3 = quant(w, 4.0f, 0.5f, o3);
    oc = (float)(i0 + 8 * i1 + 40 * i2 + 200 * i3);
}

// 256-bit global load (sm_100+): 8 fp32 per thread, contiguous.
__device__ __forceinline__ void ldg256(const float* p, float* r) {
    asm volatile(
        "ld.global.nc.v8.f32 {%0, %1, %2, %3, %4, %5, %6, %7}, [%8];"
        : "=f"(r[0]), "=f"(r[1]), "=f"(r[2]), "=f"(r[3]),
          "=f"(r[4]), "=f"(r[5]), "=f"(r[6]), "=f"(r[7])
        : "l"(p));
}

// 128-bit store, L1 no-allocate (write-once stream; L2 policy default).
__device__ __forceinline__ void stg128_noalloc(float4* p, const float4& v) {
    asm volatile(
        "st.global.L1::no_allocate.v4.f32 [%0], {%1, %2, %3, %4};"
        :: "l"(p), "f"(v.x), "f"(v.y), "f"(v.z), "f"(v.w)
        : "memory");
}

__global__ __launch_bounds__(NTHREADS) void fsq_kernel(const float* __restrict__ x,
                                                       float4* __restrict__ out4) {
    int t = blockIdx.x * NTHREADS + threadIdx.x;   // one thread = 4 tokens (16 floats)

    float v[16];
    ldg256(x + 16 * t, v);
    ldg256(x + 16 * t + 8, v + 8);

    float4 z0, z1, z2, z3, zc;
    do_token(v[0],  v[1],  v[2],  v[3],  z0.x, z1.x, z2.x, z3.x, zc.x);
    do_token(v[4],  v[5],  v[6],  v[7],  z0.y, z1.y, z2.y, z3.y, zc.y);
    do_token(v[8],  v[9],  v[10], v[11], z0.z, z1.z, z2.z, z3.z, zc.z);
    do_token(v[12], v[13], v[14], v[15], z0.w, z1.w, z2.w, z3.w, zc.w);

    const int PN4 = FSQ_N / 4;   // plane size in float4 units
    stg128_noalloc(&out4[0 * PN4 + t], z0);
    stg128_noalloc(&out4[1 * PN4 + t], z1);
    stg128_noalloc(&out4[2 * PN4 + t], z2);
    stg128_noalloc(&out4[3 * PN4 + t], z3);
    stg128_noalloc(&out4[4 * PN4 + t], zc);
}

extern "C" void kernel_launch(void* const* d_in, const int* in_sizes, int n_in,
                              void* d_out, int out_size) {
    const float* x = (const float*)d_in[0];
    float4* out4 = (float4*)d_out;
    fsq_kernel<<<NBLOCKS, NTHREADS>>>(x, out4);
}